// round 3
// baseline (speedup 1.0000x reference)
#include <cuda_runtime.h>
#include <cuda_bf16.h>

// GConv: agg = segment_sum(concat(feat[src], edge_feat), dst); out = feat + agg@W + b
// Phase 1: zero 32MB scratch accumulator (device global; no allocs allowed)
// Phase 2: edge scatter with vectorized global reductions (red.global.add.v4.f32)
// Phase 3: [N,160]x[160,128] GEMM with W in smem, 8-row register blocking, fused bias+residual
//
// NOTE: src/dst are int32 (JAX x64 disabled downcasts jnp.int64 -> int32).

#define MAX_NODES 50000
#define AGG_DIM   160
#define F_DIM     128
#define E_DIM     32

__device__ __align__(128) float g_agg[(size_t)MAX_NODES * AGG_DIM];

// ---------------------------------------------------------------------------
// Phase 1: zero the accumulator
// ---------------------------------------------------------------------------
__global__ void zero_kernel(int n4) {
    float4* p = reinterpret_cast<float4*>(g_agg);
    const float4 z = make_float4(0.f, 0.f, 0.f, 0.f);
    int stride = gridDim.x * blockDim.x;
    for (int i = blockIdx.x * blockDim.x + threadIdx.x; i < n4; i += stride)
        p[i] = z;
}

// ---------------------------------------------------------------------------
// Phase 2: one warp per edge. 32 lanes each carry a float4 of the 128-dim
// src feature; lanes 0..7 also carry a float4 of the 32-dim edge feature.
// Vectorized reductions: 40 red.v4 per edge instead of 160 scalar atomics.
// ---------------------------------------------------------------------------
__device__ __forceinline__ void red_add_v4(float* addr, float4 v) {
    asm volatile("red.global.add.v4.f32 [%0], {%1, %2, %3, %4};"
                 :: "l"(addr), "f"(v.x), "f"(v.y), "f"(v.z), "f"(v.w)
                 : "memory");
}

__global__ void scatter_kernel(const float* __restrict__ feat,
                               const float* __restrict__ edge_feat,
                               const int* __restrict__ src,
                               const int* __restrict__ dst,
                               int E, int N) {
    int warp = (blockIdx.x * blockDim.x + threadIdx.x) >> 5;
    int lane = threadIdx.x & 31;
    if (warp >= E) return;

    int s = src[warp];
    int d = dst[warp];
    if ((unsigned)s >= (unsigned)N || (unsigned)d >= (unsigned)N) return;

    const float4* hsrc = reinterpret_cast<const float4*>(feat + (long long)s * F_DIM);
    float4 hv = hsrc[lane];
    float* base = g_agg + (long long)d * AGG_DIM;
    red_add_v4(base + lane * 4, hv);

    if (lane < E_DIM / 4) {
        const float4* esrc = reinterpret_cast<const float4*>(edge_feat + (long long)warp * E_DIM);
        float4 ev = esrc[lane];
        red_add_v4(base + F_DIM + lane * 4, ev);
    }
}

// ---------------------------------------------------------------------------
// Phase 3: GEMM + bias + residual.
// blockDim = 128 (thread = output column). W [160,128] lives in smem (80KB).
// 8 rows per pass, accumulators in registers; per k-iter: 1 smem W load +
// 8 broadcast A loads + 8 FMA -> smem phases stay under the FMA budget.
// ---------------------------------------------------------------------------
#define RPB 8
#define GEMM_SMEM ((AGG_DIM * F_DIM + RPB * AGG_DIM) * (int)sizeof(float))  // 87040

__global__ void gemm_kernel(const float* __restrict__ feat,
                            const float* __restrict__ W,
                            const float* __restrict__ b,
                            float* __restrict__ out,
                            int N) {
    extern __shared__ float sh[];
    float* Wsh = sh;                      // AGG_DIM * F_DIM floats (80KB)
    float* Ash = sh + AGG_DIM * F_DIM;    // RPB * AGG_DIM floats (5KB)

    const int tid = threadIdx.x;          // 0..127, output column

    // cooperative W load (vectorized)
    {
        float4* Wv = reinterpret_cast<float4*>(Wsh);
        const float4* Wg = reinterpret_cast<const float4*>(W);
        const int n4 = AGG_DIM * F_DIM / 4;   // 5120
        for (int i = tid; i < n4; i += 128) Wv[i] = Wg[i];
    }
    const float bias = b[tid];
    __syncthreads();

    const int nchunks = (N + RPB - 1) / RPB;
    for (int chunk = blockIdx.x; chunk < nchunks; chunk += gridDim.x) {
        const int row0 = chunk * RPB;
        const int nrows = min(RPB, N - row0);

        // load RPB agg rows into smem (vectorized, coalesced)
        {
            const float4* Ag = reinterpret_cast<const float4*>(g_agg + (long long)row0 * AGG_DIM);
            float4* Av = reinterpret_cast<float4*>(Ash);
            const int n4 = nrows * AGG_DIM / 4;   // <= 320
            for (int i = tid; i < n4; i += 128) Av[i] = Ag[i];
        }
        __syncthreads();

        float acc[RPB];
#pragma unroll
        for (int r = 0; r < RPB; r++) acc[r] = bias;

#pragma unroll 4
        for (int k = 0; k < AGG_DIM; k++) {
            const float w = Wsh[k * F_DIM + tid];
#pragma unroll
            for (int r = 0; r < RPB; r++)
                acc[r] += Ash[r * AGG_DIM + k] * w;
        }

#pragma unroll
        for (int r = 0; r < RPB; r++) {
            if (r < nrows) {
                const long long off = (long long)(row0 + r) * F_DIM + tid;
                out[off] = feat[off] + acc[r];
            }
        }
        __syncthreads();
    }
}

// ---------------------------------------------------------------------------
// Launch
// ---------------------------------------------------------------------------
extern "C" void kernel_launch(void* const* d_in, const int* in_sizes, int n_in,
                              void* d_out, int out_size) {
    const float* feat      = (const float*)d_in[0];
    const float* edge_feat = (const float*)d_in[1];
    const int*   src       = (const int*)d_in[2];
    const int*   dst       = (const int*)d_in[3];
    const float* W         = (const float*)d_in[4];
    const float* b         = (const float*)d_in[5];
    float*       out       = (float*)d_out;

    const int N = out_size / F_DIM;       // 50000 (out is [N,128])
    const int E = in_sizes[2];            // 800000

    // Phase 1: zero accumulator (N*160 floats = N*40 float4)
    zero_kernel<<<2048, 256>>>(N * (AGG_DIM / 4));

    // Phase 2: scatter (one warp per edge)
    if (E > 0) {
        long long total_threads = (long long)E * 32;
        int blocks = (int)((total_threads + 255) / 256);
        scatter_kernel<<<blocks, 256>>>(feat, edge_feat, src, dst, E, N);
    }

    // Phase 3: GEMM (+bias +residual)
    {
        cudaFuncSetAttribute(gemm_kernel, cudaFuncAttributeMaxDynamicSharedMemorySize, GEMM_SMEM);
        gemm_kernel<<<296, 128, GEMM_SMEM>>>(feat, W, b, out, N);
    }
}